// round 4
// baseline (speedup 1.0000x reference)
#include <cuda_runtime.h>
#include <cuda_bf16.h>

// Problem constants (shapes fixed by the reference setup_inputs):
//   L = 512, Lp = 64, K = 17, features_dim = 56
// Output layout (float32, out_size elements):
//   [0 .. L*3K*56*56)   features_poses  (broadcast of pred_poses flat (L,3K))
//   [out_size-1]        loss scalar
#define L_DIM   512
#define LP_DIM  64
#define K_DIM   17
#define CH_DIM  (3 * K_DIM)          // 51
#define SPAT    (56 * 56)            // 3136 floats per channel
#define VEC_PER_CH (SPAT / 4)        // 784 float4 per channel

__device__ float g_partial[L_DIM];

// -------------------------------------------------------------------------
// Kernel 1: broadcast fill.  out[l, j, :, :] = pred_poses_flat[l*51 + j]
// Store-bound: 327.5 MB of float4 stores, ~100 KB of (L1/L2-cached) reads.
// -------------------------------------------------------------------------
__global__ void fill_kernel(const float* __restrict__ src,
                            float4* __restrict__ out,
                            unsigned nvec)
{
    unsigned i = blockIdx.x * blockDim.x + threadIdx.x;
    unsigned stride = gridDim.x * blockDim.x;
    for (; i < nvec; i += stride) {
        // 784 vectors per channel; div-by-const -> mulhi+shift
        float v = __ldg(&src[i / (unsigned)VEC_PER_CH]);
        out[i] = make_float4(v, v, v, v);
    }
}

// -------------------------------------------------------------------------
// Kernel 2: per-l partial loss.  One block per l (512 blocks x 64 threads),
// one thread per lp.  Per-l logf/xy hoisted into shared once per block.
// -------------------------------------------------------------------------
__global__ void loss_partial_kernel(const float* __restrict__ pred_poses,   // (L, K, 3)
                                    const float* __restrict__ target_poses, // (Lp, K, 3)
                                    const float* __restrict__ pred_fb,      // (L,)
                                    const float* __restrict__ ious,         // (L, Lp)
                                    const float* __restrict__ areas)        // (Lp,)
{
    const int l  = blockIdx.x;
    const int lp = threadIdx.x;   // 0..63

    __shared__ float s_px[K_DIM], s_py[K_DIM], s_logp[K_DIM], s_log1mp[K_DIM];

    if (lp < K_DIM) {
        const float* pp = pred_poses + (l * K_DIM + lp) * 3;
        float x = pp[0], y = pp[1], v = pp[2];
        v = fminf(fmaxf(v, 1e-7f), 1.0f - 1e-7f);
        s_px[lp]     = x;
        s_py[lp]     = y;
        s_logp[lp]   = logf(v);
        s_log1mp[lp] = logf(1.0f - v);
    }
    __syncthreads();

    const float inv2a = 1.0f / (2.0f * areas[lp] + 1e-6f);

    float fb_sum  = 0.0f;
    float bce_sum = 0.0f;
#pragma unroll
    for (int k = 0; k < K_DIM; k++) {
        const float* tp = target_poses + (lp * K_DIM + k) * 3;
        float tx = tp[0], ty = tp[1], tv = tp[2];
        float dx = s_px[k] - tx;
        float dy = s_py[k] - ty;
        float d2 = dx * dx + dy * dy;
        fb_sum  += expf(-d2 * inv2a);
        bce_sum -= tv * s_logp[k] + (1.0f - tv) * s_log1mp[k];
    }

    const float inv_k = 1.0f / (float)K_DIM;
    float tfb = fb_sum * inv_k;
    float fl  = pred_fb[l] - tfb;
    fl *= fl;
    float bce = bce_sum * inv_k;
    float s   = ious[l * LP_DIM + lp] * (fl + bce);

    // reduce 64 values (2 warps) deterministically
#pragma unroll
    for (int off = 16; off > 0; off >>= 1)
        s += __shfl_down_sync(0xffffffffu, s, off);

    __shared__ float wsum[2];
    if ((threadIdx.x & 31) == 0) wsum[threadIdx.x >> 5] = s;
    __syncthreads();
    if (threadIdx.x == 0) g_partial[l] = wsum[0] + wsum[1];
}

// -------------------------------------------------------------------------
// Kernel 3: deterministic tree reduction of 512 partials -> loss scalar.
// -------------------------------------------------------------------------
__global__ void loss_reduce_kernel(float* __restrict__ loss_out)
{
    __shared__ float sh[L_DIM];
    int t = threadIdx.x;
    sh[t] = g_partial[t];
    __syncthreads();
#pragma unroll
    for (int off = L_DIM / 2; off > 0; off >>= 1) {
        if (t < off) sh[t] += sh[t + off];
        __syncthreads();
    }
    if (t == 0) loss_out[0] = sh[0];
}

// -------------------------------------------------------------------------
extern "C" void kernel_launch(void* const* d_in, const int* in_sizes, int n_in,
                              void* d_out, int out_size)
{
    const float* pred_poses   = (const float*)d_in[0]; // (512,17,3)
    const float* target_poses = (const float*)d_in[1]; // (64,17,3)
    const float* pred_fb      = (const float*)d_in[2]; // (512,)
    const float* ious         = (const float*)d_in[3]; // (512,64)
    const float* areas        = (const float*)d_in[4]; // (64,)
    // d_in[5] = features_dim (int32) -- implied by out_size, unused

    float* out = (float*)d_out;

    // ---- loss (tiny, issue first) ----
    loss_partial_kernel<<<L_DIM, LP_DIM>>>(pred_poses, target_poses,
                                           pred_fb, ious, areas);
    loss_reduce_kernel<<<1, L_DIM>>>(out + (out_size - 1));

    // ---- broadcast fill (dominant: 327.5 MB stores) ----
    unsigned n_feat = (unsigned)(out_size - 1);       // 81,887,232
    unsigned nvec   = n_feat / 4u;                    // 20,471,808 float4
    int threads = 256;
    int blocks  = 4736;                               // 148 SMs * 32 blocks
    fill_kernel<<<blocks, threads>>>(pred_poses, (float4*)out, nvec);
}

// round 5
// speedup vs baseline: 1.1188x; 1.1188x over previous
#include <cuda_runtime.h>
#include <cuda_bf16.h>

// Shapes fixed by the reference setup_inputs:
//   L = 512, Lp = 64, K = 17, features_dim = 56
// Output layout (float32, out_size elements):
//   [0 .. L*51*56*56)    features_poses (broadcast of pred_poses flat (L,51))
//   [out_size-1]         loss scalar
#define L_DIM      512
#define LP_DIM     64
#define K_DIM      17
#define SPAT       (56 * 56)        // 3136 floats per channel
#define VEC_PER_CH (SPAT / 4)       // 784 float4 per channel

#define NB_LOSS    128              // 4 l-rows per block, 512 total
#define NB_FILL    4736             // 148 SMs * 32
#define THREADS    256

__device__ float    g_partial[L_DIM];
__device__ unsigned g_ticket = 0;

// ---------------------------------------------------------------------------
// Fused kernel.
//   blockIdx.x <  NB_LOSS : loss partials (4 l-rows each); last block reduces
//   blockIdx.x >= NB_LOSS : broadcast fill (store-bound, 327.5 MB)
// Loss blocks are first so they land in wave 1 and overlap the fill stream.
// ---------------------------------------------------------------------------
__global__ void __launch_bounds__(THREADS)
fused_kernel(const float* __restrict__ pred_poses,    // (512,17,3)
             const float* __restrict__ target_poses,  // (64,17,3)
             const float* __restrict__ pred_fb,       // (512,)
             const float* __restrict__ ious,          // (512,64)
             const float* __restrict__ areas,         // (64,)
             float*       __restrict__ out,           // (out_size,)
             unsigned nvec,                           // float4 count of features
             float*       __restrict__ loss_out)      // &out[out_size-1]
{
    const int tid = threadIdx.x;

    if (blockIdx.x >= NB_LOSS) {
        // ----------------- broadcast fill -----------------
        float4* __restrict__ ov = (float4*)out;
        unsigned i      = (blockIdx.x - NB_LOSS) * THREADS + tid;
        unsigned stride = NB_FILL * THREADS;
        for (; i < nvec; i += stride) {
            float v = __ldg(&pred_poses[i / (unsigned)VEC_PER_CH]);
            ov[i] = make_float4(v, v, v, v);
        }
        return;
    }

    // ----------------- loss partials: 4 l-rows per block -----------------
    const int l_sub = tid >> 6;           // 0..3
    const int lp    = tid & 63;           // 0..63
    const int l     = blockIdx.x * 4 + l_sub;

    __shared__ float s_px[4][K_DIM], s_py[4][K_DIM];
    __shared__ float s_logp[4][K_DIM], s_log1mp[4][K_DIM];

    if (lp < K_DIM) {
        const float* pp = pred_poses + (l * K_DIM + lp) * 3;
        float x = pp[0], y = pp[1], v = pp[2];
        v = fminf(fmaxf(v, 1e-7f), 1.0f - 1e-7f);
        s_px[l_sub][lp]     = x;
        s_py[l_sub][lp]     = y;
        s_logp[l_sub][lp]   = logf(v);
        s_log1mp[l_sub][lp] = logf(1.0f - v);
    }
    __syncthreads();

    const float inv2a = 1.0f / (2.0f * areas[lp] + 1e-6f);

    float fb_sum  = 0.0f;
    float bce_sum = 0.0f;
#pragma unroll
    for (int k = 0; k < K_DIM; k++) {
        const float* tp = target_poses + (lp * K_DIM + k) * 3;
        float tx = tp[0], ty = tp[1], tv = tp[2];
        float dx = s_px[l_sub][k] - tx;
        float dy = s_py[l_sub][k] - ty;
        float d2 = dx * dx + dy * dy;
        fb_sum  += expf(-d2 * inv2a);
        bce_sum -= tv * s_logp[l_sub][k] + (1.0f - tv) * s_log1mp[l_sub][k];
    }

    const float inv_k = 1.0f / (float)K_DIM;
    float fl  = pred_fb[l] - fb_sum * inv_k;
    fl *= fl;
    float s = ious[l * LP_DIM + lp] * (fl + bce_sum * inv_k);

    // 64 lanes per l-row = exactly 2 warps; warp shuffle then pairwise combine
#pragma unroll
    for (int off = 16; off > 0; off >>= 1)
        s += __shfl_down_sync(0xffffffffu, s, off);

    __shared__ float wsum[8];             // 8 warps per block
    if ((tid & 31) == 0) wsum[tid >> 5] = s;
    __syncthreads();
    if (lp == 0) g_partial[l] = wsum[2 * l_sub] + wsum[2 * l_sub + 1];

    // ----------------- last loss block reduces 512 -> 1 -----------------
    __shared__ unsigned s_last;
    if (tid == 0) {
        __threadfence();
        s_last = (atomicAdd(&g_ticket, 1u) == NB_LOSS - 1) ? 1u : 0u;
    }
    __syncthreads();
    if (!s_last) return;

    __shared__ float sh[THREADS];
    sh[tid] = g_partial[tid] + g_partial[tid + THREADS];
    __syncthreads();
#pragma unroll
    for (int off = THREADS / 2; off > 0; off >>= 1) {
        if (tid < off) sh[tid] += sh[tid + off];
        __syncthreads();
    }
    if (tid == 0) {
        loss_out[0] = sh[0];
        g_ticket = 0;                     // reset for graph replay
    }
}

// ---------------------------------------------------------------------------
extern "C" void kernel_launch(void* const* d_in, const int* in_sizes, int n_in,
                              void* d_out, int out_size)
{
    const float* pred_poses   = (const float*)d_in[0];
    const float* target_poses = (const float*)d_in[1];
    const float* pred_fb      = (const float*)d_in[2];
    const float* ious         = (const float*)d_in[3];
    const float* areas        = (const float*)d_in[4];

    float* out = (float*)d_out;
    unsigned nvec = (unsigned)((out_size - 1) / 4);   // 20,471,808 float4

    fused_kernel<<<NB_LOSS + NB_FILL, THREADS>>>(
        pred_poses, target_poses, pred_fb, ious, areas,
        out, nvec, out + (out_size - 1));
}